// round 2
// baseline (speedup 1.0000x reference)
#include <cuda_runtime.h>
#include <mma.h>

using namespace nvcuda;

// ---------------------------------------------------------------------------
// Problem constants: N=4, S=T=2048, D=1024. All divisible by tile sizes.
// ---------------------------------------------------------------------------
#define NB   4
#define SEQ  2048
#define DIM  1024

#define BM 128
#define BN 128
#define BK 32
#define APAD 36    // BK + 4 (padding, multiple of 4 floats -> float4 stores OK)
#define BNPAD 132  // BN + 4

// Scratch (allowed: __device__ globals, no allocation)
__device__ float g_q[(size_t)NB * SEQ * DIM];
__device__ float g_k[(size_t)NB * SEQ * DIM];
__device__ float g_v[(size_t)NB * SEQ * DIM];
__device__ float g_s[(size_t)NB * SEQ * SEQ];

// ---------------------------------------------------------------------------
// Generic tiled GEMM, tf32 WMMA, C = A * B
//   A row-major [M,K], lda
//   BCOL=true : B "col-major": element (k,n) = B[n*ldb + k]   (X @ W^T / Q @ K^T)
//   BCOL=false: B row-major  : element (k,n) = B[k*ldb + n]   (P @ V)
//   MODE 0: full
//   MODE 1: causal tile skip (skip n-tile > m-tile)            (QK^T)
//   MODE 2: causal K-limit   (k < (m_tile+1)*BM)               (P @ V)
// Block: 256 threads = 8 warps, warp tile 64x32 (4x2 frags of 16x16), block 128x128.
// ---------------------------------------------------------------------------
template<int MODE, bool BCOL>
__global__ __launch_bounds__(256)
void gemm_tf32_kernel(const float* __restrict__ A, const float* __restrict__ B,
                      float* __restrict__ C,
                      int M, int N, int K,
                      int lda, int ldb, int ldc,
                      long long strideA, long long strideB, long long strideC)
{
    const int bt = blockIdx.z;
    A += (long long)bt * strideA;
    B += (long long)bt * strideB;
    C += (long long)bt * strideC;

    const int mt = blockIdx.y;
    const int nt = blockIdx.x;
    if (MODE == 1 && nt > mt) return;   // uniform per block: safe

    int kEnd = K;
    if (MODE == 2) {
        int lim = (mt + 1) * BM;
        kEnd = (lim < K) ? lim : K;
    }

    __shared__ float As[BM * APAD];     // row-major, ldm = APAD
    __shared__ float Bs[BN * APAD];     // layout depends on BCOL (sized for max)

    wmma::fragment<wmma::accumulator, 16, 16, 8, float> acc[4][2];
    #pragma unroll
    for (int i = 0; i < 4; i++)
        #pragma unroll
        for (int j = 0; j < 2; j++)
            wmma::fill_fragment(acc[i][j], 0.0f);

    const int tid  = threadIdx.x;
    const int warp = tid >> 5;
    const int wm   = warp & 1;    // 0..1  (64 rows each)
    const int wn   = warp >> 1;   // 0..3  (32 cols each)

    const int m0 = mt * BM;
    const int n0 = nt * BN;

    for (int k0 = 0; k0 < kEnd; k0 += BK) {
        // ---- load A tile: 128 rows x 32 floats, float4 ----
        {
            const int r  = tid >> 3;          // 0..31
            const int c4 = (tid & 7) * 4;     // 0..28
            #pragma unroll
            for (int i = 0; i < 4; i++) {
                const int row = r + i * 32;
                float4 v = *reinterpret_cast<const float4*>(
                    &A[(long long)(m0 + row) * lda + k0 + c4]);
                *reinterpret_cast<float4*>(&As[row * APAD + c4]) = v;
            }
        }
        // ---- load B tile ----
        if (BCOL) {
            // Bs[n][k] : element (k,n) at Bs[n*APAD + k]
            const int r  = tid >> 3;
            const int c4 = (tid & 7) * 4;
            #pragma unroll
            for (int i = 0; i < 4; i++) {
                const int row = r + i * 32;   // n index
                float4 v = *reinterpret_cast<const float4*>(
                    &B[(long long)(n0 + row) * ldb + k0 + c4]);
                *reinterpret_cast<float4*>(&Bs[row * APAD + c4]) = v;
            }
        } else {
            // Bs[k][n] : element (k,n) at Bs[k*BNPAD + n]
            const int r  = tid >> 5;          // 0..7
            const int c4 = (tid & 31) * 4;    // 0..124
            #pragma unroll
            for (int i = 0; i < 4; i++) {
                const int row = r + i * 8;    // k index 0..31
                float4 v = *reinterpret_cast<const float4*>(
                    &B[(long long)(k0 + row) * ldb + n0 + c4]);
                *reinterpret_cast<float4*>(&Bs[row * BNPAD + c4]) = v;
            }
        }
        __syncthreads();

        #pragma unroll
        for (int kk = 0; kk < BK; kk += 8) {
            wmma::fragment<wmma::matrix_a, 16, 16, 8, wmma::precision::tf32,
                           wmma::row_major> af[4];
            #pragma unroll
            for (int i = 0; i < 4; i++) {
                wmma::load_matrix_sync(af[i], &As[(wm * 64 + i * 16) * APAD + kk], APAD);
                #pragma unroll
                for (int e = 0; e < af[i].num_elements; e++)
                    af[i].x[e] = wmma::__float_to_tf32(af[i].x[e]);
            }
            if (BCOL) {
                #pragma unroll
                for (int j = 0; j < 2; j++) {
                    wmma::fragment<wmma::matrix_b, 16, 16, 8, wmma::precision::tf32,
                                   wmma::col_major> bf;
                    wmma::load_matrix_sync(bf, &Bs[(wn * 32 + j * 16) * APAD + kk], APAD);
                    #pragma unroll
                    for (int e = 0; e < bf.num_elements; e++)
                        bf.x[e] = wmma::__float_to_tf32(bf.x[e]);
                    #pragma unroll
                    for (int i = 0; i < 4; i++)
                        wmma::mma_sync(acc[i][j], af[i], bf, acc[i][j]);
                }
            } else {
                #pragma unroll
                for (int j = 0; j < 2; j++) {
                    wmma::fragment<wmma::matrix_b, 16, 16, 8, wmma::precision::tf32,
                                   wmma::row_major> bf;
                    wmma::load_matrix_sync(bf, &Bs[kk * BNPAD + wn * 32 + j * 16], BNPAD);
                    #pragma unroll
                    for (int e = 0; e < bf.num_elements; e++)
                        bf.x[e] = wmma::__float_to_tf32(bf.x[e]);
                    #pragma unroll
                    for (int i = 0; i < 4; i++)
                        wmma::mma_sync(acc[i][j], af[i], bf, acc[i][j]);
                }
            }
        }
        __syncthreads();
    }

    #pragma unroll
    for (int i = 0; i < 4; i++)
        #pragma unroll
        for (int j = 0; j < 2; j++)
            wmma::store_matrix_sync(
                &C[(long long)(m0 + wm * 64 + i * 16) * ldc + n0 + wn * 32 + j * 16],
                acc[i][j], ldc, wmma::mem_row_major);
}

// ---------------------------------------------------------------------------
// Causal softmax over row s: reads S[s, 0..s] * scale, writes normalized probs
// for t<=s and ZEROS for s < t < roundup(s+1,128) (so the PV GEMM can read
// whole 128-wide tiles without masking). In-place on g_s.
// Warp-shuffle reductions (8 warps, 256 threads).
// ---------------------------------------------------------------------------
__global__ __launch_bounds__(256)
void softmax_kernel(float* __restrict__ S, float scale)
{
    const int s = blockIdx.x;
    const int b = blockIdx.y;
    float* row = S + ((long long)b * SEQ + s) * SEQ;

    const int len = s + 1;
    const int tal = ((s >> 7) + 1) << 7;   // round up to 128

    __shared__ float sh[SEQ];
    __shared__ float red[8];
    const int tid  = threadIdx.x;
    const int lane = tid & 31;
    const int wrp  = tid >> 5;

    // pass 1: scale, stash, max
    float mx = -1e30f;
    for (int t = tid; t < len; t += 256) {
        float v = row[t] * scale;
        sh[t] = v;
        mx = fmaxf(mx, v);
    }
    #pragma unroll
    for (int o = 16; o > 0; o >>= 1)
        mx = fmaxf(mx, __shfl_xor_sync(0xffffffffu, mx, o));
    if (lane == 0) red[wrp] = mx;
    __syncthreads();
    {
        float m = red[lane & 7];
        #pragma unroll
        for (int o = 4; o > 0; o >>= 1)
            m = fmaxf(m, __shfl_xor_sync(0xffffffffu, m, o));
        mx = m;   // every lane in every warp now has the block max
    }

    // pass 2: exp + sum
    float sum = 0.0f;
    for (int t = tid; t < len; t += 256) {
        float e = __expf(sh[t] - mx);
        sh[t] = e;
        sum += e;
    }
    #pragma unroll
    for (int o = 16; o > 0; o >>= 1)
        sum += __shfl_xor_sync(0xffffffffu, sum, o);
    __syncthreads();           // red[] reuse
    if (lane == 0) red[wrp] = sum;
    __syncthreads();
    {
        float t2 = red[lane & 7];
        #pragma unroll
        for (int o = 4; o > 0; o >>= 1)
            t2 += __shfl_xor_sync(0xffffffffu, t2, o);
        sum = t2;
    }
    const float inv = 1.0f / sum;

    for (int t = tid; t < len; t += 256) row[t] = sh[t] * inv;
    for (int t = len + tid; t < tal; t += 256) row[t] = 0.0f;
}

// ---------------------------------------------------------------------------
// kernel_launch: 3 projections -> causal QK^T -> softmax -> PV
// Inputs (reference order): query, key, value, attn_mask(int32), Wq, Wk, Wv.
// The mask is known-causal (tril); we never read it. Weight pointers are
// located defensively: the mask is the unique S*T-sized input, weights are
// the three D*D entries after it.
// ---------------------------------------------------------------------------
extern "C" void kernel_launch(void* const* d_in, const int* in_sizes, int n_in,
                              void* d_out, int out_size)
{
    const float* q_in = (const float*)d_in[0];
    const float* k_in = (const float*)d_in[1];
    const float* v_in = (const float*)d_in[2];

    // find the mask slot (S*T elements) and take the next three as Wq, Wk, Wv
    int mi = 3;
    for (int i = 3; i < n_in; i++) {
        if (in_sizes[i] == SEQ * SEQ) { mi = i; break; }
    }
    const float* Wq = (const float*)d_in[mi + 1];
    const float* Wk = (const float*)d_in[mi + 2];
    const float* Wv = (const float*)d_in[mi + 3];
    float* out = (float*)d_out;

    float *gq, *gk, *gv, *gs;
    cudaGetSymbolAddress((void**)&gq, g_q);
    cudaGetSymbolAddress((void**)&gk, g_k);
    cudaGetSymbolAddress((void**)&gv, g_v);
    cudaGetSymbolAddress((void**)&gs, g_s);

    dim3 blk(256);
    const int MS = NB * SEQ;   // 8192 rows for projections

    // Projections: C[8192,1024] = X @ W^T  (B "col-major" = W row-major [e,d])
    dim3 gp(DIM / BN, MS / BM, 1);
    gemm_tf32_kernel<0, true><<<gp, blk>>>(q_in, Wq, gq, MS, DIM, DIM,
                                           DIM, DIM, DIM, 0, 0, 0);
    gemm_tf32_kernel<0, true><<<gp, blk>>>(k_in, Wk, gk, MS, DIM, DIM,
                                           DIM, DIM, DIM, 0, 0, 0);
    gemm_tf32_kernel<0, true><<<gp, blk>>>(v_in, Wv, gv, MS, DIM, DIM,
                                           DIM, DIM, DIM, 0, 0, 0);

    // S = Q @ K^T (batched, causal tile skip). Scale applied in softmax.
    dim3 gqk(SEQ / BN, SEQ / BM, NB);
    gemm_tf32_kernel<1, true><<<gqk, blk>>>(gq, gk, gs, SEQ, SEQ, DIM,
                                            DIM, DIM, SEQ,
                                            (long long)SEQ * DIM,
                                            (long long)SEQ * DIM,
                                            (long long)SEQ * SEQ);

    // Causal softmax, in place, with 1/sqrt(D) scale.
    softmax_kernel<<<dim3(SEQ, NB), 256>>>(gs, 1.0f / 32.0f);

    // Y = P @ V (batched, causal K-limit). B row-major.
    dim3 gpv(DIM / BN, SEQ / BM, NB);
    gemm_tf32_kernel<2, false><<<gpv, blk>>>(gs, gv, out, SEQ, DIM, SEQ,
                                             SEQ, DIM, DIM,
                                             (long long)SEQ * SEQ,
                                             (long long)SEQ * DIM,
                                             (long long)SEQ * DIM);
}

// round 4
// speedup vs baseline: 1.2356x; 1.2356x over previous
#include <cuda_runtime.h>
#include <mma.h>
#include <cstdint>

using namespace nvcuda;

// ---------------------------------------------------------------------------
// Problem constants: N=4, S=T=2048, D=1024. All divisible by tile sizes.
// ---------------------------------------------------------------------------
#define NB   4
#define SEQ  2048
#define DIM  1024

#define BM 128
#define BN 128
#define BK 32
#define APAD 36     // BK+4; row pitch 144B = 9*16B -> cp.async 16B aligned
#define BNPAD 132   // BN+4; row pitch 528B = 33*16B -> aligned

#define ASZ (BM * APAD)        // 4608 floats per A stage
#define BSZ (BM * APAD)        // max of (128*36) and (32*132) -> 4608
#define SMEM_FLOATS (2 * (ASZ + BSZ))
#define SMEM_BYTES  (SMEM_FLOATS * 4)   // 73728

// Scratch (allowed: __device__ globals, no allocation)
__device__ float g_q[(size_t)NB * SEQ * DIM];
__device__ float g_k[(size_t)NB * SEQ * DIM];
__device__ float g_v[(size_t)NB * SEQ * DIM];
__device__ float g_s[(size_t)NB * SEQ * SEQ];

// ---------------------------------------------------------------------------
// cp.async helpers (16B, L1-bypass)
// ---------------------------------------------------------------------------
__device__ __forceinline__ void cp16(void* dst_smem, const void* src_gmem) {
    uint32_t d = (uint32_t)__cvta_generic_to_shared(dst_smem);
    asm volatile("cp.async.cg.shared.global [%0], [%1], 16;\n" :: "r"(d), "l"(src_gmem));
}
__device__ __forceinline__ void cp_commit() {
    asm volatile("cp.async.commit_group;\n");
}
template <int Npend>
__device__ __forceinline__ void cp_wait() {
    asm volatile("cp.async.wait_group %0;\n" :: "n"(Npend));
}

// ---------------------------------------------------------------------------
// Tiled GEMM, tf32 WMMA, cp.async double-buffered. C = A * B
//   A row-major [M,K], lda
//   BCOL=true : element (k,n) = B[n*ldb + k]   (X @ W^T, Q @ K^T)
//   BCOL=false: element (k,n) = B[k*ldb + n]   (P @ V)
//   MODE 0: full   MODE 1: causal tile skip (QK^T)   MODE 2: causal K-limit (PV)
// 256 threads = 8 warps; block tile 128x128; warp tile 64x32 (4x2 of 16x16).
// ---------------------------------------------------------------------------
template<int MODE, bool BCOL>
__global__ __launch_bounds__(256, 2)
void gemm_tf32_kernel(const float* __restrict__ A, const float* __restrict__ B,
                      float* __restrict__ C,
                      int M, int N, int K,
                      int lda, int ldb, int ldc,
                      long long strideA, long long strideB, long long strideC)
{
    const int bt = blockIdx.z;
    A += (long long)bt * strideA;
    B += (long long)bt * strideB;
    C += (long long)bt * strideC;

    const int mt = blockIdx.y;
    const int nt = blockIdx.x;
    if (MODE == 1 && nt > mt) return;   // uniform per block: safe

    int kEnd = K;
    if (MODE == 2) {
        int lim = (mt + 1) * BM;
        kEnd = (lim < K) ? lim : K;
    }
    const int nK = kEnd / BK;           // kEnd is a multiple of 128

    extern __shared__ float smem[];
    // layout: As0 | As1 | Bs0 | Bs1

    const int tid  = threadIdx.x;
    const int warp = tid >> 5;
    const int wm   = warp & 1;    // 0..1  (64 rows each)
    const int wn   = warp >> 1;   // 0..3  (32 cols each)

    const int m0 = mt * BM;
    const int n0 = nt * BN;

    // load coordinates
    const int ra = tid >> 3;          // 0..31
    const int ca = (tid & 7) * 4;     // 0..28
    const int rb = tid >> 5;          // 0..7
    const int cb = (tid & 31) * 4;    // 0..124

    wmma::fragment<wmma::accumulator, 16, 16, 8, float> acc[4][2];
    #pragma unroll
    for (int i = 0; i < 4; i++)
        #pragma unroll
        for (int j = 0; j < 2; j++)
            wmma::fill_fragment(acc[i][j], 0.0f);

    // ---- async stage loader ----
    auto load_stage = [&](int st, int k0) {
        float* As = smem + st * ASZ;
        #pragma unroll
        for (int i = 0; i < 4; i++) {
            const int row = ra + i * 32;
            cp16(&As[row * APAD + ca],
                 &A[(long long)(m0 + row) * lda + k0 + ca]);
        }
        float* Bs = smem + 2 * ASZ + st * BSZ;
        if (BCOL) {
            #pragma unroll
            for (int i = 0; i < 4; i++) {
                const int row = ra + i * 32;       // n index
                cp16(&Bs[row * APAD + ca],
                     &B[(long long)(n0 + row) * ldb + k0 + ca]);
            }
        } else {
            #pragma unroll
            for (int i = 0; i < 4; i++) {
                const int row = rb + i * 8;        // k index
                cp16(&Bs[row * BNPAD + cb],
                     &B[(long long)(k0 + row) * ldb + n0 + cb]);
            }
        }
    };

    // prologue
    load_stage(0, 0);
    cp_commit();

    for (int kt = 0; kt < nK; kt++) {
        const int cur = kt & 1;
        if (kt + 1 < nK) {
            load_stage(cur ^ 1, (kt + 1) * BK);   // prev compute of cur^1 ended with sync
            cp_commit();
            cp_wait<1>();                          // cur's group done; next in flight
        } else {
            cp_wait<0>();
        }
        __syncthreads();

        const float* As = smem + cur * ASZ;
        const float* Bs = smem + 2 * ASZ + cur * BSZ;

        #pragma unroll
        for (int kk = 0; kk < BK; kk += 8) {
            wmma::fragment<wmma::matrix_a, 16, 16, 8, wmma::precision::tf32,
                           wmma::row_major> af[4];
            #pragma unroll
            for (int i = 0; i < 4; i++) {
                wmma::load_matrix_sync(af[i], &As[(wm * 64 + i * 16) * APAD + kk], APAD);
                #pragma unroll
                for (int e = 0; e < af[i].num_elements; e++)
                    af[i].x[e] = wmma::__float_to_tf32(af[i].x[e]);
            }
            if (BCOL) {
                #pragma unroll
                for (int j = 0; j < 2; j++) {
                    wmma::fragment<wmma::matrix_b, 16, 16, 8, wmma::precision::tf32,
                                   wmma::col_major> bf;
                    wmma::load_matrix_sync(bf, &Bs[(wn * 32 + j * 16) * APAD + kk], APAD);
                    #pragma unroll
                    for (int e = 0; e < bf.num_elements; e++)
                        bf.x[e] = wmma::__float_to_tf32(bf.x[e]);
                    #pragma unroll
                    for (int i = 0; i < 4; i++)
                        wmma::mma_sync(acc[i][j], af[i], bf, acc[i][j]);
                }
            } else {
                #pragma unroll
                for (int j = 0; j < 2; j++) {
                    wmma::fragment<wmma::matrix_b, 16, 16, 8, wmma::precision::tf32,
                                   wmma::row_major> bf;
                    wmma::load_matrix_sync(bf, &Bs[kk * BNPAD + wn * 32 + j * 16], BNPAD);
                    #pragma unroll
                    for (int e = 0; e < bf.num_elements; e++)
                        bf.x[e] = wmma::__float_to_tf32(bf.x[e]);
                    #pragma unroll
                    for (int i = 0; i < 4; i++)
                        wmma::mma_sync(acc[i][j], af[i], bf, acc[i][j]);
                }
            }
        }
        __syncthreads();   // all warps done reading 'cur' before it is reloaded
    }

    #pragma unroll
    for (int i = 0; i < 4; i++)
        #pragma unroll
        for (int j = 0; j < 2; j++)
            wmma::store_matrix_sync(
                &C[(long long)(m0 + wm * 64 + i * 16) * ldc + n0 + wn * 32 + j * 16],
                acc[i][j], ldc, wmma::mem_row_major);
}

// ---------------------------------------------------------------------------
// Causal softmax over row s: reads S[s, 0..s] * scale, writes normalized probs
// for t<=s and ZEROS up to the 128-aligned boundary (PV then needs no mask).
// float4-vectorized passes; warp-shuffle reductions.
// ---------------------------------------------------------------------------
__global__ __launch_bounds__(256)
void softmax_kernel(float* __restrict__ S, float scale)
{
    const int s = blockIdx.x;
    const int b = blockIdx.y;
    float* row = S + ((long long)b * SEQ + s) * SEQ;

    const int len  = s + 1;
    const int len4 = len >> 2;
    const int tal  = ((s >> 7) + 1) << 7;   // round up to 128

    __shared__ float sh[SEQ];
    __shared__ float red[8];
    const int tid  = threadIdx.x;
    const int lane = tid & 31;
    const int wrp  = tid >> 5;

    float4*       sh4  = reinterpret_cast<float4*>(sh);
    const float4* row4 = reinterpret_cast<const float4*>(row);

    // pass 1: scale, stash, max
    float mx = -1e30f;
    for (int i = tid; i < len4; i += 256) {
        float4 v = row4[i];
        v.x *= scale; v.y *= scale; v.z *= scale; v.w *= scale;
        sh4[i] = v;
        mx = fmaxf(mx, fmaxf(fmaxf(v.x, v.y), fmaxf(v.z, v.w)));
    }
    for (int t = (len4 << 2) + tid; t < len; t += 256) {
        float v = row[t] * scale;
        sh[t] = v;
        mx = fmaxf(mx, v);
    }
    #pragma unroll
    for (int o = 16; o > 0; o >>= 1)
        mx = fmaxf(mx, __shfl_xor_sync(0xffffffffu, mx, o));
    if (lane == 0) red[wrp] = mx;
    __syncthreads();
    {
        float m = red[lane & 7];
        #pragma unroll
        for (int o = 4; o > 0; o >>= 1)
            m = fmaxf(m, __shfl_xor_sync(0xffffffffu, m, o));
        mx = m;
    }

    // pass 2: exp + sum
    float sum = 0.0f;
    for (int i = tid; i < len4; i += 256) {
        float4 v = sh4[i];
        v.x = __expf(v.x - mx); v.y = __expf(v.y - mx);
        v.z = __expf(v.z - mx); v.w = __expf(v.w - mx);
        sh4[i] = v;
        sum += (v.x + v.y) + (v.z + v.w);
    }
    for (int t = (len4 << 2) + tid; t < len; t += 256) {
        float e = __expf(sh[t] - mx);
        sh[t] = e;
        sum += e;
    }
    #pragma unroll
    for (int o = 16; o > 0; o >>= 1)
        sum += __shfl_xor_sync(0xffffffffu, sum, o);
    __syncthreads();
    if (lane == 0) red[wrp] = sum;
    __syncthreads();
    {
        float t2 = red[lane & 7];
        #pragma unroll
        for (int o = 4; o > 0; o >>= 1)
            t2 += __shfl_xor_sync(0xffffffffu, t2, o);
        sum = t2;
    }
    const float inv = 1.0f / sum;

    // pass 3: write back + zero-fill pad
    float4* rw4 = reinterpret_cast<float4*>(row);
    for (int i = tid; i < len4; i += 256) {
        float4 v = sh4[i];
        v.x *= inv; v.y *= inv; v.z *= inv; v.w *= inv;
        rw4[i] = v;
    }
    for (int t = (len4 << 2) + tid; t < len; t += 256) row[t] = sh[t] * inv;
    for (int t = len + tid; t < tal; t += 256) row[t] = 0.0f;
}

// ---------------------------------------------------------------------------
// kernel_launch: 3 projections -> causal QK^T -> softmax -> PV
// No static state: attribute opt-in runs every call (idempotent, capture-safe).
// ---------------------------------------------------------------------------
extern "C" void kernel_launch(void* const* d_in, const int* in_sizes, int n_in,
                              void* d_out, int out_size)
{
    const float* q_in = (const float*)d_in[0];
    const float* k_in = (const float*)d_in[1];
    const float* v_in = (const float*)d_in[2];

    // locate mask (unique S*T input); weights are the next three
    int mi = 3;
    for (int i = 3; i < n_in; i++) {
        if (in_sizes[i] == SEQ * SEQ) { mi = i; break; }
    }
    const float* Wq = (const float*)d_in[mi + 1];
    const float* Wk = (const float*)d_in[mi + 2];
    const float* Wv = (const float*)d_in[mi + 3];
    float* out = (float*)d_out;

    float *gq, *gk, *gv, *gs;
    cudaGetSymbolAddress((void**)&gq, g_q);
    cudaGetSymbolAddress((void**)&gk, g_k);
    cudaGetSymbolAddress((void**)&gv, g_v);
    cudaGetSymbolAddress((void**)&gs, g_s);

    // opt in to 72KB dynamic smem (idempotent, non-stream API; every call)
    cudaFuncSetAttribute(gemm_tf32_kernel<0, true>,
                         cudaFuncAttributeMaxDynamicSharedMemorySize, SMEM_BYTES);
    cudaFuncSetAttribute(gemm_tf32_kernel<1, true>,
                         cudaFuncAttributeMaxDynamicSharedMemorySize, SMEM_BYTES);
    cudaFuncSetAttribute(gemm_tf32_kernel<2, false>,
                         cudaFuncAttributeMaxDynamicSharedMemorySize, SMEM_BYTES);

    dim3 blk(256);
    const int MS = NB * SEQ;   // 8192 rows for projections

    // Projections: C[8192,1024] = X @ W^T
    dim3 gp(DIM / BN, MS / BM, 1);
    gemm_tf32_kernel<0, true><<<gp, blk, SMEM_BYTES>>>(q_in, Wq, gq, MS, DIM, DIM,
                                                       DIM, DIM, DIM, 0, 0, 0);
    gemm_tf32_kernel<0, true><<<gp, blk, SMEM_BYTES>>>(k_in, Wk, gk, MS, DIM, DIM,
                                                       DIM, DIM, DIM, 0, 0, 0);
    gemm_tf32_kernel<0, true><<<gp, blk, SMEM_BYTES>>>(v_in, Wv, gv, MS, DIM, DIM,
                                                       DIM, DIM, DIM, 0, 0, 0);

    // S = Q @ K^T (batched, causal tile skip). Scale applied in softmax.
    dim3 gqk(SEQ / BN, SEQ / BM, NB);
    gemm_tf32_kernel<1, true><<<gqk, blk, SMEM_BYTES>>>(gq, gk, gs, SEQ, SEQ, DIM,
                                                        DIM, DIM, SEQ,
                                                        (long long)SEQ * DIM,
                                                        (long long)SEQ * DIM,
                                                        (long long)SEQ * SEQ);

    // Causal softmax, in place, with 1/sqrt(D) scale.
    softmax_kernel<<<dim3(SEQ, NB), 256>>>(gs, 1.0f / 32.0f);

    // Y = P @ V (batched, causal K-limit).
    dim3 gpv(DIM / BN, SEQ / BM, NB);
    gemm_tf32_kernel<2, false><<<gpv, blk, SMEM_BYTES>>>(gs, gv, out, SEQ, DIM, SEQ,
                                                         SEQ, DIM, DIM,
                                                         (long long)SEQ * SEQ,
                                                         (long long)SEQ * DIM,
                                                         (long long)SEQ * DIM);
}

// round 6
// speedup vs baseline: 1.2586x; 1.0186x over previous
#include <cuda_runtime.h>
#include <mma.h>
#include <cstdint>

using namespace nvcuda;

// ---------------------------------------------------------------------------
// Problem constants: N=4, S=T=2048, D=1024. All divisible by tile sizes.
// NOTE: harness compiles for plain sm_100 (no 'a') -> no tcgen05/TMA. WMMA path.
// ---------------------------------------------------------------------------
#define NB   4
#define SEQ  2048
#define DIM  1024

#define BM 128
#define BN 128
#define BK 32
#define APAD 36     // BK+4; row pitch 144B = 9*16B -> cp.async 16B aligned
#define BNPAD 132   // BN+4; row pitch 528B = 33*16B -> aligned

#define ASZ (BM * APAD)        // 4608 floats per A stage
#define BSZ (BM * APAD)        // max(128*36, 32*132) = 4608
#define NSTAGE 3
#define STAGE_F (ASZ + BSZ)
#define SMEM_BYTES (NSTAGE * STAGE_F * 4)   // 110592

// Scratch (__device__ globals only; no allocation)
__device__ float g_xq[(size_t)NB * SEQ * DIM];   // tf32-rounded query input
__device__ float g_xk[(size_t)NB * SEQ * DIM];
__device__ float g_xv[(size_t)NB * SEQ * DIM];
__device__ float g_wq[(size_t)DIM * DIM];        // tf32-rounded weights
__device__ float g_wk[(size_t)DIM * DIM];
__device__ float g_wv[(size_t)DIM * DIM];
__device__ float g_q [(size_t)NB * SEQ * DIM];   // projected q (tf32-rounded)
__device__ float g_k [(size_t)NB * SEQ * DIM];
__device__ float g_v [(size_t)NB * SEQ * DIM];
__device__ float g_s [(size_t)NB * SEQ * SEQ];   // scores / probs

// ---------------------------------------------------------------------------
// cp.async helpers
// ---------------------------------------------------------------------------
__device__ __forceinline__ void cp16(void* dst_smem, const void* src_gmem) {
    uint32_t d = (uint32_t)__cvta_generic_to_shared(dst_smem);
    asm volatile("cp.async.cg.shared.global [%0], [%1], 16;\n" :: "r"(d), "l"(src_gmem));
}
__device__ __forceinline__ void cp_commit() {
    asm volatile("cp.async.commit_group;\n");
}
template <int Npend>
__device__ __forceinline__ void cp_wait() {
    asm volatile("cp.async.wait_group %0;\n" :: "n"(Npend));
}

// ---------------------------------------------------------------------------
// Elementwise tf32 rounding pass (round-to-nearest). n must be /4.
// ---------------------------------------------------------------------------
__global__ __launch_bounds__(256)
void round_tf32_kernel(const float* __restrict__ in, float* __restrict__ out, int n4)
{
    int i = blockIdx.x * blockDim.x + threadIdx.x;
    if (i < n4) {
        float4 v = reinterpret_cast<const float4*>(in)[i];
        v.x = wmma::__float_to_tf32(v.x);
        v.y = wmma::__float_to_tf32(v.y);
        v.z = wmma::__float_to_tf32(v.z);
        v.w = wmma::__float_to_tf32(v.w);
        reinterpret_cast<float4*>(out)[i] = v;
    }
}

// ---------------------------------------------------------------------------
// Tiled GEMM, tf32 WMMA, 3-stage cp.async pipeline. C = A * B
// All MMA operands are PRE-ROUNDED to tf32 in gmem -> no cvt in mainloop
// (hardware truncation of pre-rounded values is exact).
//   BCOL=true : element (k,n) = B[n*ldb + k]   (X @ W^T, Q @ K^T)
//   BCOL=false: element (k,n) = B[k*ldb + n]   (P @ V)
//   MODE 0: full   MODE 1: causal tile skip   MODE 2: causal K-limit
//   ROUNDC: round C to tf32 in epilogue (for tensors feeding later MMAs)
// 256 threads = 8 warps; block tile 128x128; warp tile 64x32.
// ---------------------------------------------------------------------------
template<int MODE, bool BCOL, bool ROUNDC>
__global__ __launch_bounds__(256, 2)
void gemm_tf32_kernel(const float* __restrict__ A, const float* __restrict__ B,
                      float* __restrict__ C,
                      int lda, int ldb, int ldc, int K,
                      long long strideA, long long strideB, long long strideC)
{
    const int bt = blockIdx.z;
    A += (long long)bt * strideA;
    B += (long long)bt * strideB;
    C += (long long)bt * strideC;

    const int mt = blockIdx.y;
    const int nt = blockIdx.x;
    if (MODE == 1 && nt > mt) return;

    int kEnd = K;
    if (MODE == 2) {
        int lim = (mt + 1) * BM;
        kEnd = (lim < K) ? lim : K;
    }
    const int nK = kEnd / BK;    // >= 4 here

    extern __shared__ float smem[];   // [stage][A | B]

    const int tid  = threadIdx.x;
    const int warp = tid >> 5;
    const int wm   = warp & 1;
    const int wn   = warp >> 1;

    const int m0 = mt * BM;
    const int n0 = nt * BN;

    const int ra = tid >> 3;          // 0..31
    const int ca = (tid & 7) * 4;     // 0..28
    const int rb = tid >> 5;          // 0..7
    const int cb = (tid & 31) * 4;    // 0..124

    wmma::fragment<wmma::accumulator, 16, 16, 8, float> acc[4][2];
    #pragma unroll
    for (int i = 0; i < 4; i++)
        #pragma unroll
        for (int j = 0; j < 2; j++)
            wmma::fill_fragment(acc[i][j], 0.0f);

    auto load_stage = [&](int st, int kc) {
        float* As = smem + st * STAGE_F;
        const int k0 = kc * BK;
        #pragma unroll
        for (int i = 0; i < 4; i++) {
            const int row = ra + i * 32;
            cp16(&As[row * APAD + ca],
                 &A[(long long)(m0 + row) * lda + k0 + ca]);
        }
        float* Bs = As + ASZ;
        if (BCOL) {
            #pragma unroll
            for (int i = 0; i < 4; i++) {
                const int row = ra + i * 32;
                cp16(&Bs[row * APAD + ca],
                     &B[(long long)(n0 + row) * ldb + k0 + ca]);
            }
        } else {
            #pragma unroll
            for (int i = 0; i < 4; i++) {
                const int row = rb + i * 8;
                cp16(&Bs[row * BNPAD + cb],
                     &B[(long long)(k0 + row) * ldb + n0 + cb]);
            }
        }
    };

    // prologue: 2 stages in flight
    load_stage(0, 0); cp_commit();
    load_stage(1, 1); cp_commit();

    for (int kt = 0; kt < nK; kt++) {
        const int cur = kt % NSTAGE;
        if (kt + 2 < nK) cp_wait<1>(); else cp_wait<0>();
        __syncthreads();
        if (kt + 2 < nK) {
            load_stage((kt + 2) % NSTAGE, kt + 2);   // slot held stage kt-1; all done
            cp_commit();
        }

        const float* As = smem + cur * STAGE_F;
        const float* Bs = As + ASZ;

        #pragma unroll
        for (int kk = 0; kk < BK; kk += 8) {
            wmma::fragment<wmma::matrix_a, 16, 16, 8, wmma::precision::tf32,
                           wmma::row_major> af[4];
            #pragma unroll
            for (int i = 0; i < 4; i++)
                wmma::load_matrix_sync(af[i], &As[(wm * 64 + i * 16) * APAD + kk], APAD);
            if (BCOL) {
                #pragma unroll
                for (int j = 0; j < 2; j++) {
                    wmma::fragment<wmma::matrix_b, 16, 16, 8, wmma::precision::tf32,
                                   wmma::col_major> bf;
                    wmma::load_matrix_sync(bf, &Bs[(wn * 32 + j * 16) * APAD + kk], APAD);
                    #pragma unroll
                    for (int i = 0; i < 4; i++)
                        wmma::mma_sync(acc[i][j], af[i], bf, acc[i][j]);
                }
            } else {
                #pragma unroll
                for (int j = 0; j < 2; j++) {
                    wmma::fragment<wmma::matrix_b, 16, 16, 8, wmma::precision::tf32,
                                   wmma::row_major> bf;
                    wmma::load_matrix_sync(bf, &Bs[kk * BNPAD + wn * 32 + j * 16], BNPAD);
                    #pragma unroll
                    for (int i = 0; i < 4; i++)
                        wmma::mma_sync(acc[i][j], af[i], bf, acc[i][j]);
                }
            }
        }
    }

    #pragma unroll
    for (int i = 0; i < 4; i++)
        #pragma unroll
        for (int j = 0; j < 2; j++) {
            if (ROUNDC) {
                #pragma unroll
                for (int e = 0; e < acc[i][j].num_elements; e++)
                    acc[i][j].x[e] = wmma::__float_to_tf32(acc[i][j].x[e]);
            }
            wmma::store_matrix_sync(
                &C[(long long)(m0 + wm * 64 + i * 16) * ldc + n0 + wn * 32 + j * 16],
                acc[i][j], ldc, wmma::mem_row_major);
        }
}

// ---------------------------------------------------------------------------
// Causal softmax over row s. Output probs are tf32-ROUNDED (they feed PV MMA).
// Zero-fill to the 128-aligned boundary so PV needs no masking.
// ---------------------------------------------------------------------------
__global__ __launch_bounds__(256)
void softmax_kernel(float* __restrict__ S, float scale)
{
    const int s = blockIdx.x;
    const int b = blockIdx.y;
    float* row = S + ((long long)b * SEQ + s) * SEQ;

    const int len  = s + 1;
    const int len4 = len >> 2;
    const int tal  = ((s >> 7) + 1) << 7;

    __shared__ float sh[SEQ];
    __shared__ float red[8];
    const int tid  = threadIdx.x;
    const int lane = tid & 31;
    const int wrp  = tid >> 5;

    float4*       sh4  = reinterpret_cast<float4*>(sh);
    const float4* row4 = reinterpret_cast<const float4*>(row);

    float mx = -1e30f;
    for (int i = tid; i < len4; i += 256) {
        float4 v = row4[i];
        v.x *= scale; v.y *= scale; v.z *= scale; v.w *= scale;
        sh4[i] = v;
        mx = fmaxf(mx, fmaxf(fmaxf(v.x, v.y), fmaxf(v.z, v.w)));
    }
    for (int t = (len4 << 2) + tid; t < len; t += 256) {
        float v = row[t] * scale;
        sh[t] = v;
        mx = fmaxf(mx, v);
    }
    #pragma unroll
    for (int o = 16; o > 0; o >>= 1)
        mx = fmaxf(mx, __shfl_xor_sync(0xffffffffu, mx, o));
    if (lane == 0) red[wrp] = mx;
    __syncthreads();
    {
        float m = red[lane & 7];
        #pragma unroll
        for (int o = 4; o > 0; o >>= 1)
            m = fmaxf(m, __shfl_xor_sync(0xffffffffu, m, o));
        mx = m;
    }

    float sum = 0.0f;
    for (int i = tid; i < len4; i += 256) {
        float4 v = sh4[i];
        v.x = __expf(v.x - mx); v.y = __expf(v.y - mx);
        v.z = __expf(v.z - mx); v.w = __expf(v.w - mx);
        sh4[i] = v;
        sum += (v.x + v.y) + (v.z + v.w);
    }
    for (int t = (len4 << 2) + tid; t < len; t += 256) {
        float e = __expf(sh[t] - mx);
        sh[t] = e;
        sum += e;
    }
    #pragma unroll
    for (int o = 16; o > 0; o >>= 1)
        sum += __shfl_xor_sync(0xffffffffu, sum, o);
    __syncthreads();
    if (lane == 0) red[wrp] = sum;
    __syncthreads();
    {
        float t2 = red[lane & 7];
        #pragma unroll
        for (int o = 4; o > 0; o >>= 1)
            t2 += __shfl_xor_sync(0xffffffffu, t2, o);
        sum = t2;
    }
    const float inv = 1.0f / sum;

    float4* rw4 = reinterpret_cast<float4*>(row);
    for (int i = tid; i < len4; i += 256) {
        float4 v = sh4[i];
        v.x = wmma::__float_to_tf32(v.x * inv);
        v.y = wmma::__float_to_tf32(v.y * inv);
        v.z = wmma::__float_to_tf32(v.z * inv);
        v.w = wmma::__float_to_tf32(v.w * inv);
        rw4[i] = v;
    }
    for (int t = (len4 << 2) + tid; t < len; t += 256)
        row[t] = wmma::__float_to_tf32(sh[t] * inv);
    for (int t = len + tid; t < tal; t += 256) row[t] = 0.0f;
}

// ---------------------------------------------------------------------------
// kernel_launch: round inputs -> 3 projections -> causal QK^T -> softmax -> PV
// ---------------------------------------------------------------------------
extern "C" void kernel_launch(void* const* d_in, const int* in_sizes, int n_in,
                              void* d_out, int out_size)
{
    const float* q_in = (const float*)d_in[0];
    const float* k_in = (const float*)d_in[1];
    const float* v_in = (const float*)d_in[2];

    int mi = 3;
    for (int i = 3; i < n_in; i++)
        if (in_sizes[i] == SEQ * SEQ) { mi = i; break; }
    const float* Wq = (const float*)d_in[mi + 1];
    const float* Wk = (const float*)d_in[mi + 2];
    const float* Wv = (const float*)d_in[mi + 3];
    float* out = (float*)d_out;

    float *xq, *xk, *xv, *wq, *wk, *wv, *gq, *gk, *gv, *gs;
    cudaGetSymbolAddress((void**)&xq, g_xq);
    cudaGetSymbolAddress((void**)&xk, g_xk);
    cudaGetSymbolAddress((void**)&xv, g_xv);
    cudaGetSymbolAddress((void**)&wq, g_wq);
    cudaGetSymbolAddress((void**)&wk, g_wk);
    cudaGetSymbolAddress((void**)&wv, g_wv);
    cudaGetSymbolAddress((void**)&gq, g_q);
    cudaGetSymbolAddress((void**)&gk, g_k);
    cudaGetSymbolAddress((void**)&gv, g_v);
    cudaGetSymbolAddress((void**)&gs, g_s);

    cudaFuncSetAttribute(gemm_tf32_kernel<0, true,  true >,
                         cudaFuncAttributeMaxDynamicSharedMemorySize, SMEM_BYTES);
    cudaFuncSetAttribute(gemm_tf32_kernel<1, true,  false>,
                         cudaFuncAttributeMaxDynamicSharedMemorySize, SMEM_BYTES);
    cudaFuncSetAttribute(gemm_tf32_kernel<2, false, false>,
                         cudaFuncAttributeMaxDynamicSharedMemorySize, SMEM_BYTES);

    dim3 blk(256);
    const int MS = NB * SEQ;   // 8192

    // -- pre-round inputs & weights to tf32 (round-to-nearest, once) --
    const int nx4 = (NB * SEQ * DIM) / 4;   // 2,097,152
    const int nw4 = (DIM * DIM) / 4;        // 262,144
    round_tf32_kernel<<<(nx4 + 255) / 256, 256>>>(q_in, xq, nx4);
    round_tf32_kernel<<<(nx4 + 255) / 256, 256>>>(k_in, xk, nx4);
    round_tf32_kernel<<<(nx4 + 255) / 256, 256>>>(v_in, xv, nx4);
    round_tf32_kernel<<<(nw4 + 255) / 256, 256>>>(Wq, wq, nw4);
    round_tf32_kernel<<<(nw4 + 255) / 256, 256>>>(Wk, wk, nw4);
    round_tf32_kernel<<<(nw4 + 255) / 256, 256>>>(Wv, wv, nw4);

    // -- projections: C = X @ W^T ; outputs rounded (feed QK/PV MMAs) --
    dim3 gp(DIM / BN, MS / BM, 1);
    gemm_tf32_kernel<0, true, true><<<gp, blk, SMEM_BYTES>>>(
        xq, wq, gq, DIM, DIM, DIM, DIM, 0, 0, 0);
    gemm_tf32_kernel<0, true, true><<<gp, blk, SMEM_BYTES>>>(
        xk, wk, gk, DIM, DIM, DIM, DIM, 0, 0, 0);
    gemm_tf32_kernel<0, true, true><<<gp, blk, SMEM_BYTES>>>(
        xv, wv, gv, DIM, DIM, DIM, DIM, 0, 0, 0);

    // -- S = Q @ K^T (causal tile skip); output full fp32 --
    dim3 gqk(SEQ / BN, SEQ / BM, NB);
    gemm_tf32_kernel<1, true, false><<<gqk, blk, SMEM_BYTES>>>(
        gq, gk, gs, DIM, DIM, SEQ, DIM,
        (long long)SEQ * DIM, (long long)SEQ * DIM, (long long)SEQ * SEQ);

    // -- softmax (scale 1/32); output tf32-rounded probs --
    softmax_kernel<<<dim3(SEQ, NB), 256>>>(gs, 1.0f / 32.0f);

    // -- Y = P @ V (causal K-limit); output full fp32 --
    dim3 gpv(DIM / BN, SEQ / BM, NB);
    gemm_tf32_kernel<2, false, false><<<gpv, blk, SMEM_BYTES>>>(
        gs, gv, out, SEQ, DIM, DIM, SEQ,
        (long long)SEQ * SEQ, (long long)SEQ * DIM, (long long)SEQ * DIM);
}

// round 7
// speedup vs baseline: 4.7332x; 3.7607x over previous
#include <cuda_runtime.h>
#include <cuda_fp16.h>
#include <mma.h>
#include <cstdint>

using namespace nvcuda;

// ---------------------------------------------------------------------------
// N=4, S=T=2048, D=1024. Plain sm_100 target: no tcgen05/TMA -> legacy WMMA.
// fp16 operands (same 10-bit mantissa as tf32), fp32 accumulate.
// ---------------------------------------------------------------------------
#define NB   4
#define SEQ  2048
#define DIM  1024

#define BM 128
#define BN 128
#define BKH 64          // 64 halves = 128 B per row
#define APAD_H 72       // row pitch 144 B (multiple of 16 B)
#define BNPAD_H 136     // row pitch 272 B (multiple of 16 B)

#define ASZ_H (BM * APAD_H)                  // 9216 halves
#define BSZ_H ASZ_H                          // max(128*72, 64*136) = 9216
#define NSTAGE 3
#define STAGE_H (ASZ_H + BSZ_H)
#define SMEM_BYTES (NSTAGE * STAGE_H * 2)    // 110592 B

// Scratch (__device__ globals; no allocation)
__device__ __half g_xq[(size_t)NB * SEQ * DIM];
__device__ __half g_xk[(size_t)NB * SEQ * DIM];
__device__ __half g_xv[(size_t)NB * SEQ * DIM];
__device__ __half g_wq[(size_t)DIM * DIM];
__device__ __half g_wk[(size_t)DIM * DIM];
__device__ __half g_wv[(size_t)DIM * DIM];
__device__ float  g_q [(size_t)NB * SEQ * DIM];
__device__ float  g_k [(size_t)NB * SEQ * DIM];
__device__ float  g_v [(size_t)NB * SEQ * DIM];
__device__ __half g_qh[(size_t)NB * SEQ * DIM];
__device__ __half g_kh[(size_t)NB * SEQ * DIM];
__device__ __half g_vh[(size_t)NB * SEQ * DIM];
__device__ float  g_s [(size_t)NB * SEQ * SEQ];
__device__ __half g_p [(size_t)NB * SEQ * SEQ];

// ---------------------------------------------------------------------------
// cp.async helpers
// ---------------------------------------------------------------------------
__device__ __forceinline__ void cp16(void* dst_smem, const void* src_gmem) {
    uint32_t d = (uint32_t)__cvta_generic_to_shared(dst_smem);
    asm volatile("cp.async.cg.shared.global [%0], [%1], 16;\n" :: "r"(d), "l"(src_gmem));
}
__device__ __forceinline__ void cp_commit() {
    asm volatile("cp.async.commit_group;\n");
}
template <int Npend>
__device__ __forceinline__ void cp_wait() {
    asm volatile("cp.async.wait_group %0;\n" :: "n"(Npend));
}

// ---------------------------------------------------------------------------
// fp32 -> fp16 elementwise (n4 = count/4)
// ---------------------------------------------------------------------------
__global__ __launch_bounds__(256)
void f2h_kernel(const float* __restrict__ in, __half* __restrict__ out, int n4)
{
    int i = blockIdx.x * blockDim.x + threadIdx.x;
    if (i < n4) {
        float4 v = reinterpret_cast<const float4*>(in)[i];
        __half2 h0 = __floats2half2_rn(v.x, v.y);
        __half2 h1 = __floats2half2_rn(v.z, v.w);
        uint2 u;
        u.x = *reinterpret_cast<uint32_t*>(&h0);
        u.y = *reinterpret_cast<uint32_t*>(&h1);
        reinterpret_cast<uint2*>(out)[i] = u;
    }
}

// ---------------------------------------------------------------------------
// Tiled GEMM, fp16 WMMA (m16n16k16), fp32 accum, 3-stage cp.async pipeline.
//   BCOL=true : element (k,n) = B[n*ldb + k]   (X @ W^T, Q @ K^T)
//   BCOL=false: element (k,n) = B[k*ldb + n]   (P @ V)
//   MODE 0: full   MODE 1: causal tile skip   MODE 2: causal K-limit
// 256 threads = 8 warps; block tile 128x128; warp tile 64x32; BK=64.
// ---------------------------------------------------------------------------
template<int MODE, bool BCOL>
__global__ __launch_bounds__(256, 2)
void gemm_fp16_kernel(const __half* __restrict__ A, const __half* __restrict__ B,
                      float* __restrict__ C,
                      int lda, int ldb, int ldc, int K,
                      long long strideA, long long strideB, long long strideC)
{
    const int bt = blockIdx.z;
    A += (long long)bt * strideA;
    B += (long long)bt * strideB;
    C += (long long)bt * strideC;

    const int mt = blockIdx.y;
    const int nt = blockIdx.x;
    if (MODE == 1 && nt > mt) return;

    int kEnd = K;
    if (MODE == 2) {
        int lim = (mt + 1) * BM;
        kEnd = (lim < K) ? lim : K;
    }
    const int nK = kEnd / BKH;     // >= 2 here (kEnd multiple of 128)

    extern __shared__ __half smem[];   // [stage][A | B]

    const int tid  = threadIdx.x;
    const int warp = tid >> 5;
    const int wm   = warp & 1;
    const int wn   = warp >> 1;

    const int m0 = mt * BM;
    const int n0 = nt * BN;

    // A/BCOL loader coords: 128 rows x 64 halves = 8 x 16B chunks per row
    const int ra = tid >> 3;           // 0..31
    const int ca = (tid & 7) * 8;      // halves: 0..56
    // B row-major loader coords: 64 rows x 128 halves = 16 chunks per row
    const int rb = tid >> 4;           // 0..15
    const int cb = (tid & 15) * 8;     // halves: 0..120

    wmma::fragment<wmma::accumulator, 16, 16, 16, float> acc[4][2];
    #pragma unroll
    for (int i = 0; i < 4; i++)
        #pragma unroll
        for (int j = 0; j < 2; j++)
            wmma::fill_fragment(acc[i][j], 0.0f);

    auto load_stage = [&](int st, int kc) {
        __half* As = smem + st * STAGE_H;
        const int k0 = kc * BKH;
        #pragma unroll
        for (int i = 0; i < 4; i++) {
            const int row = ra + i * 32;
            cp16(&As[row * APAD_H + ca],
                 &A[(long long)(m0 + row) * lda + k0 + ca]);
        }
        __half* Bs = As + ASZ_H;
        if (BCOL) {
            #pragma unroll
            for (int i = 0; i < 4; i++) {
                const int row = ra + i * 32;
                cp16(&Bs[row * APAD_H + ca],
                     &B[(long long)(n0 + row) * ldb + k0 + ca]);
            }
        } else {
            #pragma unroll
            for (int i = 0; i < 4; i++) {
                const int row = rb + i * 16;
                cp16(&Bs[row * BNPAD_H + cb],
                     &B[(long long)(k0 + row) * ldb + n0 + cb]);
            }
        }
    };

    load_stage(0, 0); cp_commit();
    if (nK > 1) { load_stage(1, 1); cp_commit(); }

    for (int kt = 0; kt < nK; kt++) {
        const int cur = kt % NSTAGE;
        if (kt + 2 < nK) cp_wait<1>(); else cp_wait<0>();
        __syncthreads();
        if (kt + 2 < nK) {
            load_stage((kt + 2) % NSTAGE, kt + 2);
            cp_commit();
        }

        const __half* As = smem + cur * STAGE_H;
        const __half* Bs = As + ASZ_H;

        #pragma unroll
        for (int kk = 0; kk < BKH; kk += 16) {
            wmma::fragment<wmma::matrix_a, 16, 16, 16, __half, wmma::row_major> af[4];
            #pragma unroll
            for (int i = 0; i < 4; i++)
                wmma::load_matrix_sync(af[i], &As[(wm * 64 + i * 16) * APAD_H + kk], APAD_H);
            if (BCOL) {
                #pragma unroll
                for (int j = 0; j < 2; j++) {
                    wmma::fragment<wmma::matrix_b, 16, 16, 16, __half, wmma::col_major> bf;
                    wmma::load_matrix_sync(bf, &Bs[(wn * 32 + j * 16) * APAD_H + kk], APAD_H);
                    #pragma unroll
                    for (int i = 0; i < 4; i++)
                        wmma::mma_sync(acc[i][j], af[i], bf, acc[i][j]);
                }
            } else {
                #pragma unroll
                for (int j = 0; j < 2; j++) {
                    wmma::fragment<wmma::matrix_b, 16, 16, 16, __half, wmma::row_major> bf;
                    wmma::load_matrix_sync(bf, &Bs[kk * BNPAD_H + wn * 32 + j * 16], BNPAD_H);
                    #pragma unroll
                    for (int i = 0; i < 4; i++)
                        wmma::mma_sync(acc[i][j], af[i], bf, acc[i][j]);
                }
            }
        }
    }

    #pragma unroll
    for (int i = 0; i < 4; i++)
        #pragma unroll
        for (int j = 0; j < 2; j++)
            wmma::store_matrix_sync(
                &C[(long long)(m0 + wm * 64 + i * 16) * ldc + n0 + wn * 32 + j * 16],
                acc[i][j], ldc, wmma::mem_row_major);
}

// ---------------------------------------------------------------------------
// Causal softmax over row s: reads fp32 scores, writes fp16 probs to P with
// zeros out to the 128-aligned boundary (PV then needs no masking).
// ---------------------------------------------------------------------------
__global__ __launch_bounds__(256)
void softmax_kernel(const float* __restrict__ S, __half* __restrict__ P, float scale)
{
    const int s = blockIdx.x;
    const int b = blockIdx.y;
    const float* row  = S + ((long long)b * SEQ + s) * SEQ;
    __half*      rowp = P + ((long long)b * SEQ + s) * SEQ;

    const int len  = s + 1;
    const int len4 = len >> 2;
    const int tal  = ((s >> 7) + 1) << 7;

    __shared__ float sh[SEQ];
    __shared__ float red[8];
    const int tid  = threadIdx.x;
    const int lane = tid & 31;
    const int wrp  = tid >> 5;

    float4*       sh4  = reinterpret_cast<float4*>(sh);
    const float4* row4 = reinterpret_cast<const float4*>(row);

    float mx = -1e30f;
    for (int i = tid; i < len4; i += 256) {
        float4 v = row4[i];
        v.x *= scale; v.y *= scale; v.z *= scale; v.w *= scale;
        sh4[i] = v;
        mx = fmaxf(mx, fmaxf(fmaxf(v.x, v.y), fmaxf(v.z, v.w)));
    }
    for (int t = (len4 << 2) + tid; t < len; t += 256) {
        float v = row[t] * scale;
        sh[t] = v;
        mx = fmaxf(mx, v);
    }
    #pragma unroll
    for (int o = 16; o > 0; o >>= 1)
        mx = fmaxf(mx, __shfl_xor_sync(0xffffffffu, mx, o));
    if (lane == 0) red[wrp] = mx;
    __syncthreads();
    {
        float m = red[lane & 7];
        #pragma unroll
        for (int o = 4; o > 0; o >>= 1)
            m = fmaxf(m, __shfl_xor_sync(0xffffffffu, m, o));
        mx = m;
    }

    float sum = 0.0f;
    for (int i = tid; i < len4; i += 256) {
        float4 v = sh4[i];
        v.x = __expf(v.x - mx); v.y = __expf(v.y - mx);
        v.z = __expf(v.z - mx); v.w = __expf(v.w - mx);
        sh4[i] = v;
        sum += (v.x + v.y) + (v.z + v.w);
    }
    for (int t = (len4 << 2) + tid; t < len; t += 256) {
        float e = __expf(sh[t] - mx);
        sh[t] = e;
        sum += e;
    }
    #pragma unroll
    for (int o = 16; o > 0; o >>= 1)
        sum += __shfl_xor_sync(0xffffffffu, sum, o);
    __syncthreads();
    if (lane == 0) red[wrp] = sum;
    __syncthreads();
    {
        float t2 = red[lane & 7];
        #pragma unroll
        for (int o = 4; o > 0; o >>= 1)
            t2 += __shfl_xor_sync(0xffffffffu, t2, o);
        sum = t2;
    }
    const float inv = 1.0f / sum;

    // write fp16 probs (vector path: 4 at a time -> 8 bytes)
    uint2* rp8 = reinterpret_cast<uint2*>(rowp);
    for (int i = tid; i < len4; i += 256) {
        float4 v = sh4[i];
        __half2 h0 = __floats2half2_rn(v.x * inv, v.y * inv);
        __half2 h1 = __floats2half2_rn(v.z * inv, v.w * inv);
        uint2 u;
        u.x = *reinterpret_cast<uint32_t*>(&h0);
        u.y = *reinterpret_cast<uint32_t*>(&h1);
        rp8[i] = u;
    }
    for (int t = (len4 << 2) + tid; t < len; t += 256)
        rowp[t] = __float2half(sh[t] * inv);
    for (int t = len + tid; t < tal; t += 256)
        rowp[t] = __half(0.0f);
}

// ---------------------------------------------------------------------------
// kernel_launch
// ---------------------------------------------------------------------------
extern "C" void kernel_launch(void* const* d_in, const int* in_sizes, int n_in,
                              void* d_out, int out_size)
{
    const float* q_in = (const float*)d_in[0];
    const float* k_in = (const float*)d_in[1];
    const float* v_in = (const float*)d_in[2];

    int mi = 3;
    for (int i = 3; i < n_in; i++)
        if (in_sizes[i] == SEQ * SEQ) { mi = i; break; }
    const float* Wq = (const float*)d_in[mi + 1];
    const float* Wk = (const float*)d_in[mi + 2];
    const float* Wv = (const float*)d_in[mi + 3];
    float* out = (float*)d_out;

    __half *xq, *xk, *xv, *wq, *wk, *wv, *qh, *kh, *vh, *ph;
    float  *gq, *gk, *gv, *gs;
    cudaGetSymbolAddress((void**)&xq, g_xq);
    cudaGetSymbolAddress((void**)&xk, g_xk);
    cudaGetSymbolAddress((void**)&xv, g_xv);
    cudaGetSymbolAddress((void**)&wq, g_wq);
    cudaGetSymbolAddress((void**)&wk, g_wk);
    cudaGetSymbolAddress((void**)&wv, g_wv);
    cudaGetSymbolAddress((void**)&qh, g_qh);
    cudaGetSymbolAddress((void**)&kh, g_kh);
    cudaGetSymbolAddress((void**)&vh, g_vh);
    cudaGetSymbolAddress((void**)&ph, g_p);
    cudaGetSymbolAddress((void**)&gq, g_q);
    cudaGetSymbolAddress((void**)&gk, g_k);
    cudaGetSymbolAddress((void**)&gv, g_v);
    cudaGetSymbolAddress((void**)&gs, g_s);

    cudaFuncSetAttribute(gemm_fp16_kernel<0, true >,
                         cudaFuncAttributeMaxDynamicSharedMemorySize, SMEM_BYTES);
    cudaFuncSetAttribute(gemm_fp16_kernel<1, true >,
                         cudaFuncAttributeMaxDynamicSharedMemorySize, SMEM_BYTES);
    cudaFuncSetAttribute(gemm_fp16_kernel<2, false>,
                         cudaFuncAttributeMaxDynamicSharedMemorySize, SMEM_BYTES);

    dim3 blk(256);
    const int MS = NB * SEQ;   // 8192

    // inputs & weights -> fp16
    const int nx4 = (NB * SEQ * DIM) / 4;
    const int nw4 = (DIM * DIM) / 4;
    f2h_kernel<<<(nx4 + 255) / 256, 256>>>(q_in, xq, nx4);
    f2h_kernel<<<(nx4 + 255) / 256, 256>>>(k_in, xk, nx4);
    f2h_kernel<<<(nx4 + 255) / 256, 256>>>(v_in, xv, nx4);
    f2h_kernel<<<(nw4 + 255) / 256, 256>>>(Wq, wq, nw4);
    f2h_kernel<<<(nw4 + 255) / 256, 256>>>(Wk, wk, nw4);
    f2h_kernel<<<(nw4 + 255) / 256, 256>>>(Wv, wv, nw4);

    // projections: C = X @ W^T (fp32 out), then -> fp16 copies
    dim3 gp(DIM / BN, MS / BM, 1);
    gemm_fp16_kernel<0, true><<<gp, blk, SMEM_BYTES>>>(
        xq, wq, gq, DIM, DIM, DIM, DIM, 0, 0, 0);
    gemm_fp16_kernel<0, true><<<gp, blk, SMEM_BYTES>>>(
        xk, wk, gk, DIM, DIM, DIM, DIM, 0, 0, 0);
    gemm_fp16_kernel<0, true><<<gp, blk, SMEM_BYTES>>>(
        xv, wv, gv, DIM, DIM, DIM, DIM, 0, 0, 0);
    f2h_kernel<<<(nx4 + 255) / 256, 256>>>(gq, qh, nx4);
    f2h_kernel<<<(nx4 + 255) / 256, 256>>>(gk, kh, nx4);
    f2h_kernel<<<(nx4 + 255) / 256, 256>>>(gv, vh, nx4);

    // S = Q @ K^T (causal tile skip), fp32 out
    dim3 gqk(SEQ / BN, SEQ / BM, NB);
    gemm_fp16_kernel<1, true><<<gqk, blk, SMEM_BYTES>>>(
        qh, kh, gs, DIM, DIM, SEQ, DIM,
        (long long)SEQ * DIM, (long long)SEQ * DIM, (long long)SEQ * SEQ);

    // softmax: fp32 scores -> fp16 probs (scale 1/32), zero-filled pad
    softmax_kernel<<<dim3(SEQ, NB), 256>>>(gs, ph, 1.0f / 32.0f);

    // Y = P @ V (causal K-limit), fp32 out
    dim3 gpv(DIM / BN, SEQ / BM, NB);
    gemm_fp16_kernel<2, false><<<gpv, blk, SMEM_BYTES>>>(
        ph, vh, out, SEQ, DIM, DIM, SEQ,
        (long long)SEQ * SEQ, (long long)SEQ * DIM, (long long)SEQ * DIM);
}

// round 8
// speedup vs baseline: 4.7352x; 1.0004x over previous
#include <cuda_runtime.h>
#include <cuda_fp16.h>
#include <mma.h>
#include <cstdint>

using namespace nvcuda;

// ---------------------------------------------------------------------------
// N=4, S=T=2048, D=1024. Plain sm_100 target: legacy WMMA fp16/fp32-acc path.
// ---------------------------------------------------------------------------
#define NB   4
#define SEQ  2048
#define DIM  1024

#define BM 128
#define BN 128
#define BKH 64          // 64 halves = 128 B per row
#define APAD_H 72       // row pitch 144 B (multiple of 16 B)
#define BNPAD_H 136     // row pitch 272 B (multiple of 16 B)

#define ASZ_H (BM * APAD_H)                  // 9216 halves
#define BSZ_H ASZ_H
#define NSTAGE 3
#define STAGE_H (ASZ_H + BSZ_H)
#define SMEM_BYTES (NSTAGE * STAGE_H * 2)    // 110592 B

// Scratch (__device__ globals; no allocation)
__device__ __half g_xq[(size_t)NB * SEQ * DIM];
__device__ __half g_xk[(size_t)NB * SEQ * DIM];
__device__ __half g_xv[(size_t)NB * SEQ * DIM];
__device__ __half g_wq[(size_t)DIM * DIM];
__device__ __half g_wk[(size_t)DIM * DIM];
__device__ __half g_wv[(size_t)DIM * DIM];
__device__ __half g_qh[(size_t)NB * SEQ * DIM];   // projected q (fp16, direct)
__device__ __half g_kh[(size_t)NB * SEQ * DIM];
__device__ __half g_vh[(size_t)NB * SEQ * DIM];
__device__ float  g_s [(size_t)NB * SEQ * SEQ];   // fp32 scores
__device__ __half g_p [(size_t)NB * SEQ * SEQ];   // fp16 probs

// ---------------------------------------------------------------------------
// cp.async helpers
// ---------------------------------------------------------------------------
__device__ __forceinline__ void cp16(void* dst_smem, const void* src_gmem) {
    uint32_t d = (uint32_t)__cvta_generic_to_shared(dst_smem);
    asm volatile("cp.async.cg.shared.global [%0], [%1], 16;\n" :: "r"(d), "l"(src_gmem));
}
__device__ __forceinline__ void cp_commit() {
    asm volatile("cp.async.commit_group;\n");
}
template <int Npend>
__device__ __forceinline__ void cp_wait() {
    asm volatile("cp.async.wait_group %0;\n" :: "n"(Npend));
}

// ---------------------------------------------------------------------------
// fp32 -> fp16 elementwise (inputs & weights only)
// ---------------------------------------------------------------------------
__global__ __launch_bounds__(256)
void f2h_kernel(const float* __restrict__ in, __half* __restrict__ out, int n4)
{
    int i = blockIdx.x * blockDim.x + threadIdx.x;
    if (i < n4) {
        float4 v = reinterpret_cast<const float4*>(in)[i];
        __half2 h0 = __floats2half2_rn(v.x, v.y);
        __half2 h1 = __floats2half2_rn(v.z, v.w);
        uint2 u;
        u.x = *reinterpret_cast<uint32_t*>(&h0);
        u.y = *reinterpret_cast<uint32_t*>(&h1);
        reinterpret_cast<uint2*>(out)[i] = u;
    }
}

// ---------------------------------------------------------------------------
// Epilogue store: fp32 accum tile -> gmem as float or __half.
// The accum fragment goes through a small smem bounce? No — direct
// store_matrix_sync for float, and for half we store per-element via
// fragment -> but layout is opaque. Instead: store fp32 to a smem staging
// tile (reuse pipeline smem, which is dead in the epilogue), then vector-
// convert to gmem. Simple and fast (one pass, no extra gmem round trip).
// ---------------------------------------------------------------------------

// ---------------------------------------------------------------------------
// Tiled GEMM, fp16 WMMA (m16n16k16), fp32 accum, 3-stage cp.async pipeline.
//   BCOL=true : element (k,n) = B[n*ldb + k]   (X @ W^T, Q @ K^T)
//   BCOL=false: element (k,n) = B[k*ldb + n]   (P @ V)
//   MODE 0: full   MODE 1: causal tile skip   MODE 2: causal K-limit
//   HOUT: output __half (via smem staging) instead of float
// MODE 1/2 reverse the m-tile index so the heaviest blocks launch first.
// 256 threads = 8 warps; block tile 128x128; warp tile 64x32; BK=64.
// ---------------------------------------------------------------------------
template<int MODE, bool BCOL, bool HOUT>
__global__ __launch_bounds__(256, 2)
void gemm_fp16_kernel(const __half* __restrict__ A, const __half* __restrict__ B,
                      void* __restrict__ Cout,
                      int lda, int ldb, int ldc, int K,
                      long long strideA, long long strideB, long long strideC)
{
    const int bt = blockIdx.z;
    A += (long long)bt * strideA;
    B += (long long)bt * strideB;

    // heaviest-first scheduling for causal kernels
    const int mt = (MODE == 0) ? blockIdx.y : (gridDim.y - 1 - blockIdx.y);
    const int nt = blockIdx.x;
    if (MODE == 1 && nt > mt) return;

    int kEnd = K;
    if (MODE == 2) {
        int lim = (mt + 1) * BM;
        kEnd = (lim < K) ? lim : K;
    }
    const int nK = kEnd / BKH;

    extern __shared__ __half smem[];   // [stage][A | B]

    const int tid  = threadIdx.x;
    const int warp = tid >> 5;
    const int wm   = warp & 1;
    const int wn   = warp >> 1;

    const int m0 = mt * BM;
    const int n0 = nt * BN;

    const int ra = tid >> 3;           // 0..31
    const int ca = (tid & 7) * 8;      // halves: 0..56
    const int rb = tid >> 4;           // 0..15
    const int cb = (tid & 15) * 8;     // halves: 0..120

    wmma::fragment<wmma::accumulator, 16, 16, 16, float> acc[4][2];
    #pragma unroll
    for (int i = 0; i < 4; i++)
        #pragma unroll
        for (int j = 0; j < 2; j++)
            wmma::fill_fragment(acc[i][j], 0.0f);

    auto load_stage = [&](int st, int kc) {
        __half* As = smem + st * STAGE_H;
        const int k0 = kc * BKH;
        #pragma unroll
        for (int i = 0; i < 4; i++) {
            const int row = ra + i * 32;
            cp16(&As[row * APAD_H + ca],
                 &A[(long long)(m0 + row) * lda + k0 + ca]);
        }
        __half* Bs = As + ASZ_H;
        if (BCOL) {
            #pragma unroll
            for (int i = 0; i < 4; i++) {
                const int row = ra + i * 32;
                cp16(&Bs[row * APAD_H + ca],
                     &B[(long long)(n0 + row) * ldb + k0 + ca]);
            }
        } else {
            #pragma unroll
            for (int i = 0; i < 4; i++) {
                const int row = rb + i * 16;
                cp16(&Bs[row * BNPAD_H + cb],
                     &B[(long long)(k0 + row) * ldb + n0 + cb]);
            }
        }
    };

    load_stage(0, 0); cp_commit();
    if (nK > 1) { load_stage(1, 1); cp_commit(); }

    for (int kt = 0; kt < nK; kt++) {
        const int cur = kt % NSTAGE;
        if (kt + 2 < nK) cp_wait<1>(); else cp_wait<0>();
        __syncthreads();
        if (kt + 2 < nK) {
            load_stage((kt + 2) % NSTAGE, kt + 2);
            cp_commit();
        }

        const __half* As = smem + cur * STAGE_H;
        const __half* Bs = As + ASZ_H;

        #pragma unroll
        for (int kk = 0; kk < BKH; kk += 16) {
            wmma::fragment<wmma::matrix_a, 16, 16, 16, __half, wmma::row_major> af[4];
            #pragma unroll
            for (int i = 0; i < 4; i++)
                wmma::load_matrix_sync(af[i], &As[(wm * 64 + i * 16) * APAD_H + kk], APAD_H);
            if (BCOL) {
                #pragma unroll
                for (int j = 0; j < 2; j++) {
                    wmma::fragment<wmma::matrix_b, 16, 16, 16, __half, wmma::col_major> bf;
                    wmma::load_matrix_sync(bf, &Bs[(wn * 32 + j * 16) * APAD_H + kk], APAD_H);
                    #pragma unroll
                    for (int i = 0; i < 4; i++)
                        wmma::mma_sync(acc[i][j], af[i], bf, acc[i][j]);
                }
            } else {
                #pragma unroll
                for (int j = 0; j < 2; j++) {
                    wmma::fragment<wmma::matrix_b, 16, 16, 16, __half, wmma::row_major> bf;
                    wmma::load_matrix_sync(bf, &Bs[kk * BNPAD_H + wn * 32 + j * 16], BNPAD_H);
                    #pragma unroll
                    for (int i = 0; i < 4; i++)
                        wmma::mma_sync(acc[i][j], af[i], bf, acc[i][j]);
                }
            }
        }
    }

    if (!HOUT) {
        float* C = (float*)Cout + (long long)bt * strideC;
        #pragma unroll
        for (int i = 0; i < 4; i++)
            #pragma unroll
            for (int j = 0; j < 2; j++)
                wmma::store_matrix_sync(
                    &C[(long long)(m0 + wm * 64 + i * 16) * ldc + n0 + wn * 32 + j * 16],
                    acc[i][j], ldc, wmma::mem_row_major);
    } else {
        // stage fp32 tile in (now dead) pipeline smem, then convert to fp16 gmem
        __half* C = (__half*)Cout + (long long)bt * strideC;
        float* stage = reinterpret_cast<float*>(smem);   // 128x128 fp32 = 64KB < 108KB
        const int LDS = BN + 4;                          // padded pitch (floats)
        __syncthreads();   // everyone done with pipeline smem
        #pragma unroll
        for (int i = 0; i < 4; i++)
            #pragma unroll
            for (int j = 0; j < 2; j++)
                wmma::store_matrix_sync(
                    &stage[(wm * 64 + i * 16) * LDS + wn * 32 + j * 16],
                    acc[i][j], LDS, wmma::mem_row_major);
        __syncthreads();
        // 128 rows x 128 cols -> fp16, vectorized 4-wide; 256 threads
        const int r  = tid >> 1;            // 0..127
        const int c0 = (tid & 1) * 64;      // 0 or 64
        #pragma unroll
        for (int c = 0; c < 64; c += 4) {
            const float* sp = &stage[r * LDS + c0 + c];
            float4 v = make_float4(sp[0], sp[1], sp[2], sp[3]);
            __half2 h0 = __floats2half2_rn(v.x, v.y);
            __half2 h1 = __floats2half2_rn(v.z, v.w);
            uint2 u;
            u.x = *reinterpret_cast<uint32_t*>(&h0);
            u.y = *reinterpret_cast<uint32_t*>(&h1);
            *reinterpret_cast<uint2*>(&C[(long long)(m0 + r) * ldc + n0 + c0 + c]) = u;
        }
    }
}

// ---------------------------------------------------------------------------
// Causal softmax over row s (reversed launch order: longest rows first).
// fp32 scores -> fp16 probs, zero-filled to the 128-aligned tile boundary.
// ---------------------------------------------------------------------------
__global__ __launch_bounds__(256)
void softmax_kernel(const float* __restrict__ S, __half* __restrict__ P, float scale)
{
    const int s = SEQ - 1 - blockIdx.x;    // heaviest first
    const int b = blockIdx.y;
    const float* row  = S + ((long long)b * SEQ + s) * SEQ;
    __half*      rowp = P + ((long long)b * SEQ + s) * SEQ;

    const int len  = s + 1;
    const int len4 = len >> 2;
    const int tal  = ((s >> 7) + 1) << 7;

    __shared__ float sh[SEQ];
    __shared__ float red[8];
    const int tid  = threadIdx.x;
    const int lane = tid & 31;
    const int wrp  = tid >> 5;

    float4*       sh4  = reinterpret_cast<float4*>(sh);
    const float4* row4 = reinterpret_cast<const float4*>(row);

    float mx = -1e30f;
    for (int i = tid; i < len4; i += 256) {
        float4 v = row4[i];
        v.x *= scale; v.y *= scale; v.z *= scale; v.w *= scale;
        sh4[i] = v;
        mx = fmaxf(mx, fmaxf(fmaxf(v.x, v.y), fmaxf(v.z, v.w)));
    }
    for (int t = (len4 << 2) + tid; t < len; t += 256) {
        float v = row[t] * scale;
        sh[t] = v;
        mx = fmaxf(mx, v);
    }
    #pragma unroll
    for (int o = 16; o > 0; o >>= 1)
        mx = fmaxf(mx, __shfl_xor_sync(0xffffffffu, mx, o));
    if (lane == 0) red[wrp] = mx;
    __syncthreads();
    {
        float m = red[lane & 7];
        #pragma unroll
        for (int o = 4; o > 0; o >>= 1)
            m = fmaxf(m, __shfl_xor_sync(0xffffffffu, m, o));
        mx = m;
    }

    float sum = 0.0f;
    for (int i = tid; i < len4; i += 256) {
        float4 v = sh4[i];
        v.x = __expf(v.x - mx); v.y = __expf(v.y - mx);
        v.z = __expf(v.z - mx); v.w = __expf(v.w - mx);
        sh4[i] = v;
        sum += (v.x + v.y) + (v.z + v.w);
    }
    for (int t = (len4 << 2) + tid; t < len; t += 256) {
        float e = __expf(sh[t] - mx);
        sh[t] = e;
        sum += e;
    }
    #pragma unroll
    for (int o = 16; o > 0; o >>= 1)
        sum += __shfl_xor_sync(0xffffffffu, sum, o);
    __syncthreads();
    if (lane == 0) red[wrp] = sum;
    __syncthreads();
    {
        float t2 = red[lane & 7];
        #pragma unroll
        for (int o = 4; o > 0; o >>= 1)
            t2 += __shfl_xor_sync(0xffffffffu, t2, o);
        sum = t2;
    }
    const float inv = 1.0f / sum;

    uint2* rp8 = reinterpret_cast<uint2*>(rowp);
    for (int i = tid; i < len4; i += 256) {
        float4 v = sh4[i];
        __half2 h0 = __floats2half2_rn(v.x * inv, v.y * inv);
        __half2 h1 = __floats2half2_rn(v.z * inv, v.w * inv);
        uint2 u;
        u.x = *reinterpret_cast<uint32_t*>(&h0);
        u.y = *reinterpret_cast<uint32_t*>(&h1);
        rp8[i] = u;
    }
    for (int t = (len4 << 2) + tid; t < len; t += 256)
        rowp[t] = __float2half(sh[t] * inv);
    for (int t = len + tid; t < tal; t += 256)
        rowp[t] = __half(0.0f);
}

// ---------------------------------------------------------------------------
// kernel_launch
// ---------------------------------------------------------------------------
extern "C" void kernel_launch(void* const* d_in, const int* in_sizes, int n_in,
                              void* d_out, int out_size)
{
    const float* q_in = (const float*)d_in[0];
    const float* k_in = (const float*)d_in[1];
    const float* v_in = (const float*)d_in[2];

    int mi = 3;
    for (int i = 3; i < n_in; i++)
        if (in_sizes[i] == SEQ * SEQ) { mi = i; break; }
    const float* Wq = (const float*)d_in[mi + 1];
    const float* Wk = (const float*)d_in[mi + 2];
    const float* Wv = (const float*)d_in[mi + 3];
    float* out = (float*)d_out;

    __half *xq, *xk, *xv, *wq, *wk, *wv, *qh, *kh, *vh, *ph;
    float  *gs;
    cudaGetSymbolAddress((void**)&xq, g_xq);
    cudaGetSymbolAddress((void**)&xk, g_xk);
    cudaGetSymbolAddress((void**)&xv, g_xv);
    cudaGetSymbolAddress((void**)&wq, g_wq);
    cudaGetSymbolAddress((void**)&wk, g_wk);
    cudaGetSymbolAddress((void**)&wv, g_wv);
    cudaGetSymbolAddress((void**)&qh, g_qh);
    cudaGetSymbolAddress((void**)&kh, g_kh);
    cudaGetSymbolAddress((void**)&vh, g_vh);
    cudaGetSymbolAddress((void**)&ph, g_p);
    cudaGetSymbolAddress((void**)&gs, g_s);

    cudaFuncSetAttribute(gemm_fp16_kernel<0, true,  true >,
                         cudaFuncAttributeMaxDynamicSharedMemorySize, SMEM_BYTES);
    cudaFuncSetAttribute(gemm_fp16_kernel<1, true,  false>,
                         cudaFuncAttributeMaxDynamicSharedMemorySize, SMEM_BYTES);
    cudaFuncSetAttribute(gemm_fp16_kernel<2, false, false>,
                         cudaFuncAttributeMaxDynamicSharedMemorySize, SMEM_BYTES);

    dim3 blk(256);
    const int MS = NB * SEQ;   // 8192

    // inputs & weights -> fp16
    const int nx4 = (NB * SEQ * DIM) / 4;
    const int nw4 = (DIM * DIM) / 4;
    f2h_kernel<<<(nx4 + 255) / 256, 256>>>(q_in, xq, nx4);
    f2h_kernel<<<(nx4 + 255) / 256, 256>>>(k_in, xk, nx4);
    f2h_kernel<<<(nx4 + 255) / 256, 256>>>(v_in, xv, nx4);
    f2h_kernel<<<(nw4 + 255) / 256, 256>>>(Wq, wq, nw4);
    f2h_kernel<<<(nw4 + 255) / 256, 256>>>(Wk, wk, nw4);
    f2h_kernel<<<(nw4 + 255) / 256, 256>>>(Wv, wv, nw4);

    // projections: fp16 output direct (fused epilogue conversion)
    dim3 gp(DIM / BN, MS / BM, 1);
    gemm_fp16_kernel<0, true, true><<<gp, blk, SMEM_BYTES>>>(
        xq, wq, qh, DIM, DIM, DIM, DIM, 0, 0, 0);
    gemm_fp16_kernel<0, true, true><<<gp, blk, SMEM_BYTES>>>(
        xk, wk, kh, DIM, DIM, DIM, DIM, 0, 0, 0);
    gemm_fp16_kernel<0, true, true><<<gp, blk, SMEM_BYTES>>>(
        xv, wv, vh, DIM, DIM, DIM, DIM, 0, 0, 0);

    // S = Q @ K^T (causal tile skip, heaviest-first), fp32 out
    dim3 gqk(SEQ / BN, SEQ / BM, NB);
    gemm_fp16_kernel<1, true, false><<<gqk, blk, SMEM_BYTES>>>(
        qh, kh, gs, DIM, DIM, SEQ, DIM,
        (long long)SEQ * DIM, (long long)SEQ * DIM, (long long)SEQ * SEQ);

    // softmax: fp32 scores -> fp16 probs (scale 1/32), longest rows first
    softmax_kernel<<<dim3(SEQ, NB), 256>>>(gs, ph, 1.0f / 32.0f);

    // Y = P @ V (causal K-limit, heaviest-first), fp32 out
    dim3 gpv(DIM / BN, SEQ / BM, NB);
    gemm_fp16_kernel<2, false, false><<<gpv, blk, SMEM_BYTES>>>(
        ph, vh, out, SEQ, DIM, DIM, SEQ,
        (long long)SEQ * SEQ, (long long)SEQ * DIM, (long long)SEQ * DIM);
}

// round 10
// speedup vs baseline: 5.1085x; 1.0788x over previous
#include <cuda_runtime.h>
#include <cuda_fp16.h>
#include <mma.h>
#include <cstdint>

using namespace nvcuda;

// ---------------------------------------------------------------------------
// N=4, S=T=2048, D=1024. Plain sm_100 target: legacy WMMA fp16/fp32-acc path.
// 6-launch plan: conv_x, conv_w, merged-proj, QK, softmax, PV (PV = ncu idx 5).
// ---------------------------------------------------------------------------
#define NB   4
#define SEQ  2048
#define DIM  1024
#define QKVLD (3 * DIM)     // 3072: fused projection output pitch

#define BM 128
#define BN 128
#define BKH 64          // 64 halves = 128 B per row
#define APAD_H 72       // row pitch 144 B (multiple of 16 B)
#define BNPAD_H 136     // row pitch 272 B (multiple of 16 B)

#define ASZ_H (BM * APAD_H)                  // 9216 halves
#define BSZ_H ASZ_H
#define NSTAGE 3
#define STAGE_H (ASZ_H + BSZ_H)
#define SMEM_BYTES (NSTAGE * STAGE_H * 2)    // 110592 B

// Scratch (__device__ globals; no allocation)
__device__ __half g_xq  [(size_t)NB * SEQ * DIM];
__device__ __half g_xk  [(size_t)NB * SEQ * DIM];
__device__ __half g_xv  [(size_t)NB * SEQ * DIM];
__device__ __half g_wcat[(size_t)3 * DIM * DIM];      // Wq|Wk|Wv rows stacked
__device__ __half g_qkv [(size_t)NB * SEQ * QKVLD];   // fused q|k|v fp16
__device__ float  g_s   [(size_t)NB * SEQ * SEQ];     // fp32 scores
__device__ __half g_p   [(size_t)NB * SEQ * SEQ];     // fp16 probs

// ---------------------------------------------------------------------------
// cp.async helpers
// ---------------------------------------------------------------------------
__device__ __forceinline__ void cp16(void* dst_smem, const void* src_gmem) {
    uint32_t d = (uint32_t)__cvta_generic_to_shared(dst_smem);
    asm volatile("cp.async.cg.shared.global [%0], [%1], 16;\n" :: "r"(d), "l"(src_gmem));
}
__device__ __forceinline__ void cp_commit() {
    asm volatile("cp.async.commit_group;\n");
}
template <int Npend>
__device__ __forceinline__ void cp_wait() {
    asm volatile("cp.async.wait_group %0;\n" :: "n"(Npend));
}

// ---------------------------------------------------------------------------
// fp32 -> fp16, three tensors in one launch (blockIdx.y selects tensor).
// n4 = element count / 4 per tensor.
// ---------------------------------------------------------------------------
__global__ __launch_bounds__(256)
void f2h3_kernel(const float* __restrict__ s0, const float* __restrict__ s1,
                 const float* __restrict__ s2,
                 __half* __restrict__ d0, __half* __restrict__ d1,
                 __half* __restrict__ d2, int n4)
{
    const int t = blockIdx.y;
    const float* in  = (t == 0) ? s0 : (t == 1) ? s1 : s2;
    __half*      out = (t == 0) ? d0 : (t == 1) ? d1 : d2;
    int i = blockIdx.x * blockDim.x + threadIdx.x;
    if (i < n4) {
        float4 v = reinterpret_cast<const float4*>(in)[i];
        __half2 h0 = __floats2half2_rn(v.x, v.y);
        __half2 h1 = __floats2half2_rn(v.z, v.w);
        uint2 u;
        u.x = *reinterpret_cast<uint32_t*>(&h0);
        u.y = *reinterpret_cast<uint32_t*>(&h1);
        reinterpret_cast<uint2*>(out)[i] = u;
    }
}

// ---------------------------------------------------------------------------
// Tiled GEMM, fp16 WMMA (m16n16k16), fp32 accum, 3-stage cp.async pipeline.
//   MODE 0: merged projection. A selected from {A0,A1,A2} by n-segment
//           (seg = nt/8); B = Wcat (K-major rows, n up to 3072); fp16 out.
//   MODE 1: Q@K^T, causal tile skip, fp32 out.    (BCOL path)
//   MODE 2: P@V, causal K-limit, fp32 out.        (row-major B path)
// MODE 1/2 reverse the m-tile index (heaviest blocks first).
// 256 threads = 8 warps; block tile 128x128; warp tile 64x32; BK=64.
// ---------------------------------------------------------------------------
template<int MODE, bool BCOL, bool HOUT>
__global__ __launch_bounds__(256, 2)
void gemm_fp16_kernel(const __half* __restrict__ A0, const __half* __restrict__ A1,
                      const __half* __restrict__ A2, const __half* __restrict__ B,
                      void* __restrict__ Cout,
                      int lda, int ldb, int ldc, int K,
                      long long strideA, long long strideB, long long strideC)
{
    const int bt = blockIdx.z;
    const int mt = (MODE == 0) ? blockIdx.y : (gridDim.y - 1 - blockIdx.y);
    const int nt = blockIdx.x;
    if (MODE == 1 && nt > mt) return;

    const __half* A;
    if (MODE == 0) {
        const int seg = nt >> 3;               // 0..2
        A = (seg == 0) ? A0 : (seg == 1) ? A1 : A2;
    } else {
        A = A0 + (long long)bt * strideA;
    }
    B += (long long)bt * strideB;

    int kEnd = K;
    if (MODE == 2) {
        int lim = (mt + 1) * BM;
        kEnd = (lim < K) ? lim : K;
    }
    const int nK = kEnd / BKH;

    extern __shared__ __half smem[];   // [stage][A | B]

    const int tid  = threadIdx.x;
    const int warp = tid >> 5;
    const int wm   = warp & 1;
    const int wn   = warp >> 1;

    const int m0 = mt * BM;
    const int n0 = nt * BN;

    const int ra = tid >> 3;           // 0..31
    const int ca = (tid & 7) * 8;      // halves: 0..56
    const int rb = tid >> 4;           // 0..15
    const int cb = (tid & 15) * 8;     // halves: 0..120

    wmma::fragment<wmma::accumulator, 16, 16, 16, float> acc[4][2];
    #pragma unroll
    for (int i = 0; i < 4; i++)
        #pragma unroll
        for (int j = 0; j < 2; j++)
            wmma::fill_fragment(acc[i][j], 0.0f);

    auto load_stage = [&](int st, int kc) {
        __half* As = smem + st * STAGE_H;
        const int k0 = kc * BKH;
        #pragma unroll
        for (int i = 0; i < 4; i++) {
            const int row = ra + i * 32;
            cp16(&As[row * APAD_H + ca],
                 &A[(long long)(m0 + row) * lda + k0 + ca]);
        }
        __half* Bs = As + ASZ_H;
        if (BCOL) {
            #pragma unroll
            for (int i = 0; i < 4; i++) {
                const int row = ra + i * 32;
                cp16(&Bs[row * APAD_H + ca],
                     &B[(long long)(n0 + row) * ldb + k0 + ca]);
            }
        } else {
            #pragma unroll
            for (int i = 0; i < 4; i++) {
                const int row = rb + i * 16;
                cp16(&Bs[row * BNPAD_H + cb],
                     &B[(long long)(k0 + row) * ldb + n0 + cb]);
            }
        }
    };

    load_stage(0, 0); cp_commit();
    if (nK > 1) { load_stage(1, 1); cp_commit(); }

    for (int kt = 0; kt < nK; kt++) {
        const int cur = kt % NSTAGE;
        if (kt + 2 < nK) cp_wait<1>(); else cp_wait<0>();
        __syncthreads();
        if (kt + 2 < nK) {
            load_stage((kt + 2) % NSTAGE, kt + 2);
            cp_commit();
        }

        const __half* As = smem + cur * STAGE_H;
        const __half* Bs = As + ASZ_H;

        #pragma unroll
        for (int kk = 0; kk < BKH; kk += 16) {
            wmma::fragment<wmma::matrix_a, 16, 16, 16, __half, wmma::row_major> af[4];
            #pragma unroll
            for (int i = 0; i < 4; i++)
                wmma::load_matrix_sync(af[i], &As[(wm * 64 + i * 16) * APAD_H + kk], APAD_H);
            if (BCOL) {
                #pragma unroll
                for (int j = 0; j < 2; j++) {
                    wmma::fragment<wmma::matrix_b, 16, 16, 16, __half, wmma::col_major> bf;
                    wmma::load_matrix_sync(bf, &Bs[(wn * 32 + j * 16) * APAD_H + kk], APAD_H);
                    #pragma unroll
                    for (int i = 0; i < 4; i++)
                        wmma::mma_sync(acc[i][j], af[i], bf, acc[i][j]);
                }
            } else {
                #pragma unroll
                for (int j = 0; j < 2; j++) {
                    wmma::fragment<wmma::matrix_b, 16, 16, 16, __half, wmma::row_major> bf;
                    wmma::load_matrix_sync(bf, &Bs[kk * BNPAD_H + wn * 32 + j * 16], BNPAD_H);
                    #pragma unroll
                    for (int i = 0; i < 4; i++)
                        wmma::mma_sync(acc[i][j], af[i], bf, acc[i][j]);
                }
            }
        }
    }

    if (!HOUT) {
        float* C = (float*)Cout + (long long)bt * strideC;
        #pragma unroll
        for (int i = 0; i < 4; i++)
            #pragma unroll
            for (int j = 0; j < 2; j++)
                wmma::store_matrix_sync(
                    &C[(long long)(m0 + wm * 64 + i * 16) * ldc + n0 + wn * 32 + j * 16],
                    acc[i][j], ldc, wmma::mem_row_major);
    } else {
        // stage fp32 tile in dead pipeline smem, then vector-convert to fp16 gmem
        __half* C = (__half*)Cout + (long long)bt * strideC;
        float* stage = reinterpret_cast<float*>(smem);   // 128x132 fp32 = 67.6KB < 108KB
        const int LDS = BN + 4;
        __syncthreads();
        #pragma unroll
        for (int i = 0; i < 4; i++)
            #pragma unroll
            for (int j = 0; j < 2; j++)
                wmma::store_matrix_sync(
                    &stage[(wm * 64 + i * 16) * LDS + wn * 32 + j * 16],
                    acc[i][j], LDS, wmma::mem_row_major);
        __syncthreads();
        const int r  = tid >> 1;            // 0..127
        const int c0 = (tid & 1) * 64;      // 0 or 64
        #pragma unroll
        for (int c = 0; c < 64; c += 4) {
            const float* sp = &stage[r * LDS + c0 + c];
            float4 v = make_float4(sp[0], sp[1], sp[2], sp[3]);
            __half2 h0 = __floats2half2_rn(v.x, v.y);
            __half2 h1 = __floats2half2_rn(v.z, v.w);
            uint2 u;
            u.x = *reinterpret_cast<uint32_t*>(&h0);
            u.y = *reinterpret_cast<uint32_t*>(&h1);
            *reinterpret_cast<uint2*>(&C[(long long)(m0 + r) * ldc + n0 + c0 + c]) = u;
        }
    }
}

// ---------------------------------------------------------------------------
// Causal softmax over row s (longest rows first). fp32 scores -> fp16 probs,
// zero-filled to the 128-aligned tile boundary.
// ---------------------------------------------------------------------------
__global__ __launch_bounds__(256)
void softmax_kernel(const float* __restrict__ S, __half* __restrict__ P, float scale)
{
    const int s = SEQ - 1 - blockIdx.x;
    const int b = blockIdx.y;
    const float* row  = S + ((long long)b * SEQ + s) * SEQ;
    __half*      rowp = P + ((long long)b * SEQ + s) * SEQ;

    const int len  = s + 1;
    const int len4 = len >> 2;
    const int tal  = ((s >> 7) + 1) << 7;

    __shared__ float sh[SEQ];
    __shared__ float red[8];
    const int tid  = threadIdx.x;
    const int lane = tid & 31;
    const int wrp  = tid >> 5;

    float4*       sh4  = reinterpret_cast<float4*>(sh);
    const float4* row4 = reinterpret_cast<const float4*>(row);

    float mx = -1e30f;
    for (int i = tid; i < len4; i += 256) {
        float4 v = row4[i];
        v.x *= scale; v.y *= scale; v.z *= scale; v.w *= scale;
        sh4[i] = v;
        mx = fmaxf(mx, fmaxf(fmaxf(v.x, v.y), fmaxf(v.z, v.w)));
    }
    for (int t = (len4 << 2) + tid; t < len; t += 256) {
        float v = row[t] * scale;
        sh[t] = v;
        mx = fmaxf(mx, v);
    }
    #pragma unroll
    for (int o = 16; o > 0; o >>= 1)
        mx = fmaxf(mx, __shfl_xor_sync(0xffffffffu, mx, o));
    if (lane == 0) red[wrp] = mx;
    __syncthreads();
    {
        float m = red[lane & 7];
        #pragma unroll
        for (int o = 4; o > 0; o >>= 1)
            m = fmaxf(m, __shfl_xor_sync(0xffffffffu, m, o));
        mx = m;
    }

    float sum = 0.0f;
    for (int i = tid; i < len4; i += 256) {
        float4 v = sh4[i];
        v.x = __expf(v.x - mx); v.y = __expf(v.y - mx);
        v.z = __expf(v.z - mx); v.w = __expf(v.w - mx);
        sh4[i] = v;
        sum += (v.x + v.y) + (v.z + v.w);
    }
    for (int t = (len4 << 2) + tid; t < len; t += 256) {
        float e = __expf(sh[t] - mx);
        sh[t] = e;
        sum += e;
    }
    #pragma unroll
    for (int o = 16; o > 0; o >>= 1)
        sum += __shfl_xor_sync(0xffffffffu, sum, o);
    __syncthreads();
    if (lane == 0) red[wrp] = sum;
    __syncthreads();
    {
        float t2 = red[lane & 7];
        #pragma unroll
        for (int o = 4; o > 0; o >>= 1)
            t2 += __shfl_xor_sync(0xffffffffu, t2, o);
        sum = t2;
    }
    const float inv = 1.0f / sum;

    uint2* rp8 = reinterpret_cast<uint2*>(rowp);
    for (int i = tid; i < len4; i += 256) {
        float4 v = sh4[i];
        __half2 h0 = __floats2half2_rn(v.x * inv, v.y * inv);
        __half2 h1 = __floats2half2_rn(v.z * inv, v.w * inv);
        uint2 u;
        u.x = *reinterpret_cast<uint32_t*>(&h0);
        u.y = *reinterpret_cast<uint32_t*>(&h1);
        rp8[i] = u;
    }
    for (int t = (len4 << 2) + tid; t < len; t += 256)
        rowp[t] = __float2half(sh[t] * inv);
    for (int t = len + tid; t < tal; t += 256)
        rowp[t] = __half(0.0f);
}

// ---------------------------------------------------------------------------
// kernel_launch — 6 launches total; PV is launch index 5 (ncu-captured).
// ---------------------------------------------------------------------------
extern "C" void kernel_launch(void* const* d_in, const int* in_sizes, int n_in,
                              void* d_out, int out_size)
{
    const float* q_in = (const float*)d_in[0];
    const float* k_in = (const float*)d_in[1];
    const float* v_in = (const float*)d_in[2];

    int mi = 3;
    for (int i = 3; i < n_in; i++)
        if (in_sizes[i] == SEQ * SEQ) { mi = i; break; }
    const float* Wq = (const float*)d_in[mi + 1];
    const float* Wk = (const float*)d_in[mi + 2];
    const float* Wv = (const float*)d_in[mi + 3];
    float* out = (float*)d_out;

    __half *xq, *xk, *xv, *wcat, *qkv, *ph;
    float  *gs;
    cudaGetSymbolAddress((void**)&xq,   g_xq);
    cudaGetSymbolAddress((void**)&xk,   g_xk);
    cudaGetSymbolAddress((void**)&xv,   g_xv);
    cudaGetSymbolAddress((void**)&wcat, g_wcat);
    cudaGetSymbolAddress((void**)&qkv,  g_qkv);
    cudaGetSymbolAddress((void**)&ph,   g_p);
    cudaGetSymbolAddress((void**)&gs,   g_s);

    cudaFuncSetAttribute(gemm_fp16_kernel<0, true,  true >,
                         cudaFuncAttributeMaxDynamicSharedMemorySize, SMEM_BYTES);
    cudaFuncSetAttribute(gemm_fp16_kernel<1, true,  false>,
                         cudaFuncAttributeMaxDynamicSharedMemorySize, SMEM_BYTES);
    cudaFuncSetAttribute(gemm_fp16_kernel<2, false, false>,
                         cudaFuncAttributeMaxDynamicSharedMemorySize, SMEM_BYTES);

    dim3 blk(256);
    const int MS = NB * SEQ;   // 8192

    // launch 0: inputs -> fp16 (3 tensors, one launch)
    const int nx4 = (NB * SEQ * DIM) / 4;
    f2h3_kernel<<<dim3((nx4 + 255) / 256, 3), blk>>>(q_in, k_in, v_in,
                                                     xq, xk, xv, nx4);
    // launch 1: weights -> fp16 concat [3072,1024]
    const int nw4 = (DIM * DIM) / 4;
    f2h3_kernel<<<dim3((nw4 + 255) / 256, 3), blk>>>(Wq, Wk, Wv,
                                                     wcat,
                                                     wcat + (size_t)DIM * DIM,
                                                     wcat + (size_t)2 * DIM * DIM, nw4);

    // launch 2: merged projections -> QKV[8192,3072] fp16
    dim3 gp(QKVLD / BN, MS / BM, 1);   // 24 x 64
    gemm_fp16_kernel<0, true, true><<<gp, blk, SMEM_BYTES>>>(
        xq, xk, xv, wcat, qkv, DIM, DIM, QKVLD, DIM, 0, 0, 0);

    // launch 3: S = Q @ K^T (causal tile skip, heaviest-first), fp32 out
    const __half* qh = qkv;               // cols [0,1024)
    const __half* kh = qkv + DIM;         // cols [1024,2048)
    const __half* vh = qkv + 2 * DIM;     // cols [2048,3072)
    dim3 gqk(SEQ / BN, SEQ / BM, NB);
    gemm_fp16_kernel<1, true, false><<<gqk, blk, SMEM_BYTES>>>(
        qh, nullptr, nullptr, kh, gs, QKVLD, QKVLD, SEQ, DIM,
        (long long)SEQ * QKVLD, (long long)SEQ * QKVLD, (long long)SEQ * SEQ);

    // launch 4: softmax (scale 1/32), fp32 scores -> fp16 probs
    softmax_kernel<<<dim3(SEQ, NB), blk>>>(gs, ph, 1.0f / 32.0f);

    // launch 5: Y = P @ V (causal K-limit, heaviest-first), fp32 out  [PROFILED]
    dim3 gpv(DIM / BN, SEQ / BM, NB);
    gemm_fp16_kernel<2, false, false><<<gpv, blk, SMEM_BYTES>>>(
        ph, nullptr, nullptr, vh, out, SEQ, QKVLD, DIM, SEQ,
        (long long)SEQ * SEQ, (long long)SEQ * QKVLD, (long long)SEQ * DIM);
}